// round 15
// baseline (speedup 1.0000x reference)
#include <cuda_runtime.h>

// CELossWithLS: focal-weighted label-smoothed CE, single fused kernel.
// logits: [B*S, C] f32 (C = 10000), target: [B*S] int32, out: scalar f32.
//
// per_tok = -( 1e-5 * sum_i (1-p_i)^3 * logs_i  +  0.9 * (1-p_t)^3 * logs_t )
// sum_i (1-p)^3 logs = (Sx - C*L) - 3*(B1/A1 - L) + O(1.5e-5 abs),
// A1 = sum e^x, B1 = sum x e^x, L = log(A1). rel_err <= 1e-6 measured.
//
// r14 compile error revealed sm_103a's 256-bit global loads (v8.b32 is the
// REQUIRED form for L2::evict_first). One volatile LDG.256 per iteration
// keeps 1024B/warp in flight per outstanding load -- 2x r13's 512B, the
// exact knife-edge (32KB/SM) that pinned every LDG variant at 73-76% DRAM --
// at HALF the load-instruction count and no double-buffer register blowup.
// Row stride 40000B % 32 == 0 -> alignment holds.
// Epilogue: r13's fence-free memory-order atomics (REDG + acq_rel pack).

#define NCLASS  10000
#define NVEC8   (NCLASS / 8)   // 1250 x 8-float chunks per row
#define THREADS 256

__device__ float              g_sum  = 0.0f;  // reset by last CTA each call
__device__ unsigned long long g_pack = 0ull;  // hi: arrivals, lo: valid count

struct f8 { float a0,a1,a2,a3,a4,a5,a6,a7; };

__device__ __forceinline__ f8 ldg_ef_v8(const float* p) {
    f8 v;
    asm volatile("ld.global.nc.L2::evict_first.v8.b32 "
                 "{%0,%1,%2,%3,%4,%5,%6,%7}, [%8];"
                 : "=f"(v.a0), "=f"(v.a1), "=f"(v.a2), "=f"(v.a3),
                   "=f"(v.a4), "=f"(v.a5), "=f"(v.a6), "=f"(v.a7)
                 : "l"(p));
    return v;
}
__device__ __forceinline__ void red_add_f32_relaxed(float* p, float v) {
    asm volatile("red.relaxed.gpu.add.f32 [%0], %1;" :: "l"(p), "f"(v) : "memory");
}
__device__ __forceinline__ unsigned long long
atom_add_u64_acqrel(unsigned long long* p, unsigned long long v) {
    unsigned long long r;
    asm volatile("atom.acq_rel.gpu.add.u64 %0, [%1], %2;"
                 : "=l"(r) : "l"(p), "l"(v) : "memory");
    return r;
}
__device__ __forceinline__ float atom_exch_f32_acquire(float* p, float v) {
    float r;
    asm volatile("atom.acquire.gpu.exch.b32 %0, [%1], %2;"
                 : "=f"(r) : "l"(p), "f"(v) : "memory");
    return r;
}

__device__ __forceinline__ void acc1(float x, float& sx, float& a1, float& b1) {
    float e = __expf(x);
    sx += x; a1 += e; b1 = fmaf(x, e, b1);
}

__global__ __launch_bounds__(THREADS, 1) void ce_fused(
    const float* __restrict__ logits,
    const int*   __restrict__ target,
    float*       __restrict__ out,
    const int    ntok)
{
    const int row = blockIdx.x;
    const int tgt = __ldg(&target[row]);

    // Hoisted target-logit load: latency overlaps the streaming loop.
    float xt = 0.0f;
    if (tgt >= 0 && tgt < NCLASS)
        xt = __ldg(&logits[(size_t)row * NCLASS + tgt]);

    const float* __restrict__ base = logits + (size_t)row * NCLASS;

    float sx = 0.0f;   // sum x
    float a1 = 0.0f;   // sum e^x
    float b1 = 0.0f;   // sum x * e^x

    // 256-bit streaming loads: 1250 chunks, stride 256 threads.
    // Threads 0..225 run 5 iters, threads 226..255 run 4.
    #pragma unroll 1
    for (int i = threadIdx.x; i < NVEC8; i += THREADS) {
        f8 v = ldg_ef_v8(base + 8 * i);
        acc1(v.a0, sx, a1, b1);
        acc1(v.a1, sx, a1, b1);
        acc1(v.a2, sx, a1, b1);
        acc1(v.a3, sx, a1, b1);
        acc1(v.a4, sx, a1, b1);
        acc1(v.a5, sx, a1, b1);
        acc1(v.a6, sx, a1, b1);
        acc1(v.a7, sx, a1, b1);
    }

    // intra-warp tree reduce (3 values)
    #pragma unroll
    for (int o = 16; o > 0; o >>= 1) {
        sx += __shfl_down_sync(0xffffffffu, sx, o);
        a1 += __shfl_down_sync(0xffffffffu, a1, o);
        b1 += __shfl_down_sync(0xffffffffu, b1, o);
    }

    __shared__ float s_sx[THREADS / 32];
    __shared__ float s_a1[THREADS / 32];
    __shared__ float s_b1[THREADS / 32];
    const int lane = threadIdx.x & 31;
    const int wrp  = threadIdx.x >> 5;
    if (lane == 0) { s_sx[wrp] = sx; s_a1[wrp] = a1; s_b1[wrp] = b1; }
    __syncthreads();

    if (threadIdx.x == 0) {
        float SX = 0.0f, A1 = 0.0f, B1 = 0.0f;
        #pragma unroll
        for (int k = 0; k < THREADS / 32; k++) {
            SX += s_sx[k]; A1 += s_a1[k]; B1 += s_b1[k];
        }

        unsigned valid = 0u;
        if (tgt != -1) {
            float L  = __logf(A1);
            float S3 = (SX - (float)NCLASS * L) - 3.0f * (B1 / A1 - L);
            float per_tok = -1e-5f * S3;
            if (tgt >= 0 && tgt < NCLASS) {
                float lt = xt - L;
                float pt = __expf(lt);
                float om = 1.0f - pt;
                per_tok -= 0.9f * om * om * om * lt;
            }
            red_add_f32_relaxed(&g_sum, per_tok);   // REDG, no fence
            valid = 1u;
        }

        // acq_rel: release orders my g_sum red before my arrival; acquire
        // (for the last arriver) makes ALL g_sum reds visible.
        unsigned long long prev =
            atom_add_u64_acqrel(&g_pack, 0x100000000ull + (unsigned long long)valid);
        unsigned arrived = (unsigned)(prev >> 32);

        if (arrived == (unsigned)(ntok - 1)) {      // last CTA
            unsigned cnt = (unsigned)(prev & 0xffffffffu) + valid;
            float total = atom_exch_f32_acquire(&g_sum, 0.0f);  // read+reset
            out[0] = total / (float)cnt;
            g_pack = 0ull;                          // reset for next replay
        }
    }
}

extern "C" void kernel_launch(void* const* d_in, const int* in_sizes, int n_in,
                              void* d_out, int out_size)
{
    const float* logits = (const float*)d_in[0];
    const int*   target = (const int*)d_in[1];
    const int ntok = in_sizes[1];          // B*S tokens

    ce_fused<<<ntok, THREADS>>>(logits, target, (float*)d_out, ntok);
}

// round 16
// speedup vs baseline: 1.1002x; 1.1002x over previous
#include <cuda_runtime.h>
#include <cstdint>

// CELossWithLS: focal-weighted label-smoothed CE, single fused kernel with a
// per-thread cp.async staging pipeline.
// logits: [B*S, C] f32 (C = 10000), target: [B*S] int32, out: scalar f32.
//
// per_tok = -( 1e-5 * sum_i (1-p_i)^3 * logs_i  +  0.9 * (1-p_t)^3 * logs_t )
// sum_i (1-p)^3 logs = (Sx - C*L) - 3*(B1/A1 - L) + O(1.5e-5 abs),
// A1 = sum e^x, B1 = sum x e^x, L = log(A1). rel_err <= 2e-6 measured.
//
// Session conclusion r4-r15: ptxas always collapses register-resident LDG
// streaming to MLP=1 (regs=30) -> 32KB in flight/SM == knife edge -> 73-76%
// DRAM, ~6 TB/s. r12's TMA failure was the BLOCK-WIDE mbarrier lockstep, not
// staging. This round: cp.async.cg (LDGSTS) -- per-THREAD commit groups, no
// barriers, zero result registers held -> ptxas cannot serialize it.
// DEPTH=6 ring, prefetch 5, wait_group(4) => 4 outstanding 16B copies/thread:
// 2048 thr/SM x 64B = 131KB in flight (4x knife edge). smem 24.6KB/CTA,
// 8 CTAs = 197KB <= 228. Each thread consumes only its own slot.
// Epilogue: r13's fence-free memory-order atomics.

#define NCLASS  10000
#define NVEC    (NCLASS / 4)        // 2500 float4 per row
#define THREADS 256
#define NITER   ((NVEC + THREADS - 1) / THREADS)   // 10
#define DEPTH   6

__device__ float              g_sum  = 0.0f;  // reset by last CTA each call
__device__ unsigned long long g_pack = 0ull;  // hi: arrivals, lo: valid count

__device__ __forceinline__ void cpa16(uint32_t saddr, const void* gsrc) {
    asm volatile("cp.async.cg.shared.global [%0], [%1], 16;"
                 :: "r"(saddr), "l"(gsrc) : "memory");
}
__device__ __forceinline__ void cpa_commit() {
    asm volatile("cp.async.commit_group;" ::: "memory");
}
template<int N> __device__ __forceinline__ void cpa_wait() {
    asm volatile("cp.async.wait_group %0;" :: "n"(N) : "memory");
}
__device__ __forceinline__ void red_add_f32_relaxed(float* p, float v) {
    asm volatile("red.relaxed.gpu.add.f32 [%0], %1;" :: "l"(p), "f"(v) : "memory");
}
__device__ __forceinline__ unsigned long long
atom_add_u64_acqrel(unsigned long long* p, unsigned long long v) {
    unsigned long long r;
    asm volatile("atom.acq_rel.gpu.add.u64 %0, [%1], %2;"
                 : "=l"(r) : "l"(p), "l"(v) : "memory");
    return r;
}
__device__ __forceinline__ float atom_exch_f32_acquire(float* p, float v) {
    float r;
    asm volatile("atom.acquire.gpu.exch.b32 %0, [%1], %2;"
                 : "=f"(r) : "l"(p), "f"(v) : "memory");
    return r;
}

__device__ __forceinline__ void proc4(const float4 v,
                                      float& sx, float& a1, float& b1) {
    float e;
    e = __expf(v.x); sx += v.x; a1 += e; b1 = fmaf(v.x, e, b1);
    e = __expf(v.y); sx += v.y; a1 += e; b1 = fmaf(v.y, e, b1);
    e = __expf(v.z); sx += v.z; a1 += e; b1 = fmaf(v.z, e, b1);
    e = __expf(v.w); sx += v.w; a1 += e; b1 = fmaf(v.w, e, b1);
}

__global__ __launch_bounds__(THREADS, 1) void ce_fused(
    const float* __restrict__ logits,
    const int*   __restrict__ target,
    float*       __restrict__ out,
    const int    ntok)
{
    __shared__ __align__(16) float4 sbuf[DEPTH][THREADS];

    const int row = blockIdx.x;
    const int tgt = __ldg(&target[row]);

    // Hoisted target-logit load: latency overlaps the streaming pipeline.
    float xt = 0.0f;
    if (tgt >= 0 && tgt < NCLASS)
        xt = __ldg(&logits[(size_t)row * NCLASS + tgt]);

    const float4* __restrict__ p =
        reinterpret_cast<const float4*>(logits) + (size_t)row * NVEC;

    const uint32_t my_slot_base =
        (uint32_t)__cvta_generic_to_shared(&sbuf[0][threadIdx.x]);
    const uint32_t slot_stride = sizeof(float4) * THREADS;   // stage stride

    // Prefetch stages 0..DEPTH-2 (per-thread groups; empty commits are legal).
    #pragma unroll
    for (int k = 0; k < DEPTH - 1; k++) {
        int idx = threadIdx.x + k * THREADS;
        if (idx < NVEC) cpa16(my_slot_base + k * slot_stride, p + idx);
        cpa_commit();
    }

    float sx = 0.0f, a1 = 0.0f, b1 = 0.0f;

    #pragma unroll
    for (int k = 0; k < NITER; k++) {
        // Keep the pipeline full: issue stage k+DEPTH-1.
        int idx_n = threadIdx.x + (k + DEPTH - 1) * THREADS;
        if (idx_n < NVEC)
            cpa16(my_slot_base + ((k + DEPTH - 1) % DEPTH) * slot_stride,
                  p + idx_n);
        cpa_commit();

        // Wait until <= DEPTH-2 groups pending -> stage k has landed.
        cpa_wait<DEPTH - 2>();

        int idx = threadIdx.x + k * THREADS;
        if (idx < NVEC)
            proc4(sbuf[k % DEPTH][threadIdx.x], sx, a1, b1);
    }

    // intra-warp tree reduce (3 values)
    #pragma unroll
    for (int o = 16; o > 0; o >>= 1) {
        sx += __shfl_down_sync(0xffffffffu, sx, o);
        a1 += __shfl_down_sync(0xffffffffu, a1, o);
        b1 += __shfl_down_sync(0xffffffffu, b1, o);
    }

    __shared__ float s_sx[THREADS / 32];
    __shared__ float s_a1[THREADS / 32];
    __shared__ float s_b1[THREADS / 32];
    const int lane = threadIdx.x & 31;
    const int wrp  = threadIdx.x >> 5;
    if (lane == 0) { s_sx[wrp] = sx; s_a1[wrp] = a1; s_b1[wrp] = b1; }
    __syncthreads();

    if (threadIdx.x == 0) {
        float SX = 0.0f, A1 = 0.0f, B1 = 0.0f;
        #pragma unroll
        for (int k = 0; k < THREADS / 32; k++) {
            SX += s_sx[k]; A1 += s_a1[k]; B1 += s_b1[k];
        }

        unsigned valid = 0u;
        if (tgt != -1) {
            float L  = __logf(A1);
            float S3 = (SX - (float)NCLASS * L) - 3.0f * (B1 / A1 - L);
            float per_tok = -1e-5f * S3;
            if (tgt >= 0 && tgt < NCLASS) {
                float lt = xt - L;
                float pt = __expf(lt);
                float om = 1.0f - pt;
                per_tok -= 0.9f * om * om * om * lt;
            }
            red_add_f32_relaxed(&g_sum, per_tok);   // REDG, no fence
            valid = 1u;
        }

        // acq_rel: release orders my g_sum red before my arrival; acquire
        // (for the last arriver) makes ALL g_sum reds visible.
        unsigned long long prev =
            atom_add_u64_acqrel(&g_pack, 0x100000000ull + (unsigned long long)valid);
        unsigned arrived = (unsigned)(prev >> 32);

        if (arrived == (unsigned)(ntok - 1)) {      // last CTA
            unsigned cnt = (unsigned)(prev & 0xffffffffu) + valid;
            float total = atom_exch_f32_acquire(&g_sum, 0.0f);  // read+reset
            out[0] = total / (float)cnt;
            g_pack = 0ull;                          // reset for next replay
        }
    }
}

extern "C" void kernel_launch(void* const* d_in, const int* in_sizes, int n_in,
                              void* d_out, int out_size)
{
    const float* logits = (const float*)d_in[0];
    const int*   target = (const int*)d_in[1];
    const int ntok = in_sizes[1];          // B*S tokens

    ce_fused<<<ntok, THREADS>>>(logits, target, (float*)d_out, ntok);
}